// round 13
// baseline (speedup 1.0000x reference)
#include <cuda_runtime.h>
#include <math.h>
#include <stdint.h>

#define T_STEPS 512
#define BATCH   64
#define IN_DIM  256
#define HID     512
#define OUT_DIM 256
#define BH      (BATCH * HID)        // 32768
#define M_ROWS  (T_STEPS * BATCH)    // 32768

// Scratch (allocation-free rule: __device__ globals)
__device__ float g_xp[(size_t)M_ROWS * HID];   // xp = x@W_ih^T + b_ih + b_hh
__device__ float g_rnn[(size_t)M_ROWS * HID];  // h history (exchange medium)

// ---- barrier state: monotonic flags + persistent epoch ----
#define SCAN_CTAS 128
#define NGROUPS   4     // batch groups
#define CGS       32    // col groups per batch group
__device__ __align__(128) unsigned g_flags2[NGROUPS][32];  // one 128B line per group
__device__ unsigned g_epoch;

__device__ __forceinline__ unsigned ld_acq(const unsigned* p) {
    unsigned v;
    asm volatile("ld.acquire.gpu.u32 %0, [%1];" : "=r"(v) : "l"(p));
    return v;
}
__device__ __forceinline__ void st_rel(unsigned* p, unsigned v) {
    asm volatile("st.release.gpu.u32 [%0], %1;" :: "l"(p), "r"(v));
}

// fast tanh: rel err ~1e-6, clamped (no NaN)
__device__ __forceinline__ float tanh_fast(float x) {
    float xc = fminf(9.0f, fmaxf(-9.0f, x));
    float e  = exp2f(2.885390081777927f * xc);   // e^(2x)
    return __fdividef(e - 1.0f, e + 1.0f);
}

#define FMA2(acc, a, b) asm("fma.rn.f32x2 %0, %1, %2, %0;" : "+l"(acc) : "l"(a), "l"(b))

// -------------------- SGEMM: C[M,N] = A[M,K] @ Bw[N,K]^T + bias --------------------
template<int BM, int BN, int BK, int TM, int TN, int THREADS>
__global__ __launch_bounds__(THREADS)
void sgemm_bt_bias(const float* __restrict__ A,
                   const float* __restrict__ Bw,
                   const float* __restrict__ bias0,
                   const float* __restrict__ bias1,
                   float* __restrict__ C,
                   int M, int N, int K)
{
    __shared__ float As[BK][BM];
    __shared__ float Bs[BK][BN];

    const int tid = threadIdx.x;
    const int tx  = tid % (BN / TN);
    const int ty  = tid / (BN / TN);
    const int m0  = blockIdx.y * BM;
    const int n0  = blockIdx.x * BN;

    float acc[TM][TN];
    #pragma unroll
    for (int i = 0; i < TM; ++i)
        #pragma unroll
        for (int j = 0; j < TN; ++j) acc[i][j] = 0.f;

    for (int k0 = 0; k0 < K; k0 += BK) {
        #pragma unroll
        for (int i = tid; i < (BM * BK) / 4; i += THREADS) {
            int r  = i / (BK / 4);
            int c4 = i % (BK / 4);
            float4 v = *(const float4*)&A[(size_t)(m0 + r) * K + k0 + c4 * 4];
            As[c4 * 4 + 0][r] = v.x;
            As[c4 * 4 + 1][r] = v.y;
            As[c4 * 4 + 2][r] = v.z;
            As[c4 * 4 + 3][r] = v.w;
        }
        #pragma unroll
        for (int i = tid; i < (BN * BK) / 4; i += THREADS) {
            int r  = i / (BK / 4);
            int c4 = i % (BK / 4);
            float4 v = *(const float4*)&Bw[(size_t)(n0 + r) * K + k0 + c4 * 4];
            Bs[c4 * 4 + 0][r] = v.x;
            Bs[c4 * 4 + 1][r] = v.y;
            Bs[c4 * 4 + 2][r] = v.z;
            Bs[c4 * 4 + 3][r] = v.w;
        }
        __syncthreads();

        #pragma unroll
        for (int kk = 0; kk < BK; ++kk) {
            float aR[TM], bR[TN];
            #pragma unroll
            for (int i = 0; i < TM; ++i) aR[i] = As[kk][ty * TM + i];
            #pragma unroll
            for (int j = 0; j < TN; ++j) bR[j] = Bs[kk][tx * TN + j];
            #pragma unroll
            for (int i = 0; i < TM; ++i)
                #pragma unroll
                for (int j = 0; j < TN; ++j)
                    acc[i][j] += aR[i] * bR[j];
        }
        __syncthreads();
    }

    float bj[TN];
    #pragma unroll
    for (int j = 0; j < TN; ++j) {
        int n = n0 + tx * TN + j;
        bj[j] = bias0[n] + (bias1 ? bias1[n] : 0.f);
    }
    #pragma unroll
    for (int i = 0; i < TM; ++i) {
        int m = m0 + ty * TM + i;
        #pragma unroll
        for (int j = 0; j < TN; ++j) {
            int n = n0 + tx * TN + j;
            C[(size_t)m * N + n] = acc[i][j] + bj[j];
        }
    }
}

// -------------------- fused scan + y GEMM (v10: no staging) --------------------
// 128 CTAs = 32 col-groups x 4 batch-groups. CTA: 16 h-cols x 16 batches,
// plus 8 y-cols x 16 batches of the output GEMM computed inside the barrier
// window. h[t-1] is read DIRECTLY from g_rnn via LDG (L1-cached, MLP-pipelined,
// interleaved with FMAs) — no SMEM staging phase on the critical path.
#define COLS_PER_CTA 16
#define BPC          16
#define OC_CTA       8            // y-cols per col-group (256/32)
#define WS           516
#define SW_F   (COLS_PER_CTA * WS)   // 8256 floats
#define SWO_F  (OC_CTA * WS)         // 4128
#define SY_F   256
#define SMEM_SCAN_BYTES ((SW_F + SWO_F + SY_F) * 4)   // 50560

__global__ __launch_bounds__(256)
void rnn_scan10(const float* __restrict__ Whh,    // [HID, HID]
                const float* __restrict__ Wout,   // [OUT_DIM, HID]
                const float* __restrict__ b_out,  // [OUT_DIM]
                float* __restrict__ y,            // [T, B, O] (d_out)
                float* __restrict__ h_out)        // [B, HID]  (d_out tail)
{
    extern __shared__ float sm[];
    float* sW  = sm;                // [16][WS]  W_hh rows (h-cols of this cg)
    float* sWo = sW + SW_F;         // [8][WS]   W_out rows (y-cols of this cg)
    float* sY  = sWo + SWO_F;       // [256] y partials (kh=1 halves)
    __shared__ unsigned s_base;

    const int tid = threadIdx.x;
    const int bid = blockIdx.x;
    const int bh  = bid & 3;
    const int cg  = bid >> 2;

    // h mapping: warp covers 8 cols x 4 batches
    const int w = tid >> 5, l = tid & 31;
    const int c  = ((w & 1) << 3) + (l & 7);     // 0..15
    const int bl = ((w >> 1) << 2) + (l >> 3);   // 0..15
    const int colg = cg * COLS_PER_CTA + c;
    const int b    = bh * BPC + bl;
    const int b0   = bh * BPC;

    // y mapping: o = tid&127 -> (yb = o>>3, oc = o&7), kh = tid>>7
    const int o   = tid & 127;
    const int yb  = o >> 3;
    const int oc  = o & 7;
    const int kh  = tid >> 7;
    const int ocg = cg * OC_CTA + oc;
    const float bo = b_out[ocg];

    if (tid == 0) s_base = *(volatile unsigned*)&g_epoch;

    // cache W_hh rows [cg*16, +16) and W_out rows [cg*8, +8)
    for (int i = tid; i < COLS_PER_CTA * (HID / 4); i += 256) {
        int r  = i >> 7;
        int k4 = i & 127;
        float4 v = *(const float4*)&Whh[(size_t)(cg * COLS_PER_CTA + r) * HID + k4 * 4];
        *(float4*)&sW[r * WS + k4 * 4] = v;
    }
    for (int i = tid; i < OC_CTA * (HID / 4); i += 256) {
        int r  = i >> 7;
        int k4 = i & 127;
        float4 v = *(const float4*)&Wout[(size_t)(cg * OC_CTA + r) * HID + k4 * 4];
        *(float4*)&sWo[r * WS + k4 * 4] = v;
    }
    __syncthreads();
    const unsigned base = s_base;

    float my_xp = g_xp[(size_t)b * HID + colg];   // t = 0

    const ulonglong2* w2  = (const ulonglong2*)&sW[c * WS];
    const ulonglong2* wo2 = (const ulonglong2*)&sWo[oc * WS] + kh * 64;

    for (int t = 0; t < T_STEPS; ++t) {
        // ---- h[t] = tanh(xp + h[t-1] @ Whh_slice^T); h[t-1] via direct LDG ----
        float acc = my_xp;
        if (t > 0) {
            const ulonglong2* h2 =
                (const ulonglong2*)&g_rnn[(size_t)(t - 1) * BH + (size_t)b * HID];
            unsigned long long a01 = 0ull, a23 = 0ull;
            #pragma unroll 8
            for (int k4 = 0; k4 < HID / 4; ++k4) {
                ulonglong2 hv = h2[k4];   // LDG.128 (L2/L1; MLP across iters)
                ulonglong2 wv = w2[k4];   // LDS.128
                FMA2(a01, hv.x, wv.x);
                FMA2(a23, hv.y, wv.y);
            }
            float s0, s1, s2, s3;
            asm("mov.b64 {%0, %1}, %2;" : "=f"(s0), "=f"(s1) : "l"(a01));
            asm("mov.b64 {%0, %1}, %2;" : "=f"(s2), "=f"(s3) : "l"(a23));
            acc += (s0 + s1) + (s2 + s3);
        }
        float hn = tanh_fast(acc);
        g_rnn[(size_t)t * BH + (size_t)b * HID + colg] = hn;
        if (t == T_STEPS - 1)
            h_out[(size_t)b * HID + colg] = hn;

        __syncthreads();                      // all h[t] stores of this CTA issued
        if (tid == 0)
            st_rel(&g_flags2[bh][cg], base + (unsigned)t + 1u);  // publish

        // ---- gap work: y[t-1] partial from g_rnn (rows L1-hot) ----
        float part = 0.f;
        if (t > 0) {
            const ulonglong2* hy2 =
                (const ulonglong2*)&g_rnn[(size_t)(t - 1) * BH + (size_t)(b0 + yb) * HID]
                + kh * 64;
            unsigned long long a01 = 0ull, a23 = 0ull;
            #pragma unroll 8
            for (int k4 = 0; k4 < 64; ++k4) {     // half of HID/4
                ulonglong2 hv = hy2[k4];
                ulonglong2 wv = wo2[k4];
                FMA2(a01, hv.x, wv.x);
                FMA2(a23, hv.y, wv.y);
            }
            float s0, s1, s2, s3;
            asm("mov.b64 {%0, %1}, %2;" : "=f"(s0), "=f"(s1) : "l"(a01));
            asm("mov.b64 {%0, %1}, %2;" : "=f"(s2), "=f"(s3) : "l"(a23));
            part = (s0 + s1) + (s2 + s3);
            if (kh) sY[o] = part;
        }

        // ---- barrier: wait for whole bh group to publish h[t] ----
        const unsigned target = base + (unsigned)t + 1u;
        if (tid < 32) {
            bool ok;
            do {
                unsigned v = ld_acq(&g_flags2[bh][tid]);
                ok = __all_sync(0xffffffffu, (int)(v - target) >= 0);
            } while (!ok);
        }
        __syncthreads();                      // flags seen; sY visible

        if (t > 0 && !kh)
            y[(size_t)(t - 1) * (BATCH * OUT_DIM) + (size_t)(b0 + yb) * OUT_DIM + ocg]
                = bo + part + sY[o];

        if (t + 1 < T_STEPS)
            my_xp = g_xp[(size_t)(t + 1) * BH + (size_t)b * HID + colg];
        // no staging sync: next-iter sY writes are separated by the post-compute
        // __syncthreads() above; h[t] reads are ordered by the flag acquire.
    }

    // ---- epilogue: y[511] from g_rnn[511] ----
    {
        const ulonglong2* hy2 =
            (const ulonglong2*)&g_rnn[(size_t)(T_STEPS - 1) * BH + (size_t)(b0 + yb) * HID]
            + kh * 64;
        unsigned long long a01 = 0ull, a23 = 0ull;
        #pragma unroll 8
        for (int k4 = 0; k4 < 64; ++k4) {
            ulonglong2 hv = hy2[k4];
            ulonglong2 wv = wo2[k4];
            FMA2(a01, hv.x, wv.x);
            FMA2(a23, hv.y, wv.y);
        }
        float s0, s1, s2, s3;
        asm("mov.b64 {%0, %1}, %2;" : "=f"(s0), "=f"(s1) : "l"(a01));
        asm("mov.b64 {%0, %1}, %2;" : "=f"(s2), "=f"(s3) : "l"(a23));
        float part = (s0 + s1) + (s2 + s3);
        if (kh) sY[o] = part;
        __syncthreads();
        if (!kh)
            y[(size_t)(T_STEPS - 1) * (BATCH * OUT_DIM) + (size_t)(b0 + yb) * OUT_DIM + ocg]
                = bo + part + sY[o];
    }

    // advance epoch for the next launch (monotonic flags)
    if (bid == 0 && tid == 0)
        *(volatile unsigned*)&g_epoch = base + (unsigned)T_STEPS;
}

__global__ void dummy_k() {}

// -------------------- launch --------------------
extern "C" void kernel_launch(void* const* d_in, const int* in_sizes, int n_in,
                              void* d_out, int out_size)
{
    const float* x     = (const float*)d_in[0];
    const float* W_ih  = (const float*)d_in[1];
    const float* W_hh  = (const float*)d_in[2];
    const float* b_ih  = (const float*)d_in[3];
    const float* b_hh  = (const float*)d_in[4];
    const float* W_out = (const float*)d_in[5];
    const float* b_out = (const float*)d_in[6];

    float* y = (float*)d_out;                             // [T,B,O]
    float* h = y + (size_t)T_STEPS * BATCH * OUT_DIM;     // [1,B,H]

    float* xp = nullptr;
    cudaGetSymbolAddress((void**)&xp, g_xp);

    // K1: xp = x @ W_ih^T + b_ih + b_hh    (M=32768, N=512, K=256)
    {
        dim3 grid(HID / 64, M_ROWS / 128);
        sgemm_bt_bias<128, 64, 16, 8, 4, 256><<<grid, 256>>>(
            x, W_ih, b_ih, b_hh, xp, M_ROWS, HID, IN_DIM);
    }

    // two dummies so the fused scan sits at global launch #6 for ncu (-s 5 -c 1)
    dummy_k<<<1, 32>>>();
    dummy_k<<<1, 32>>>();

    // K2: fused recurrence + output GEMM; writes y + h_last
    cudaFuncSetAttribute(rnn_scan10, cudaFuncAttributeMaxDynamicSharedMemorySize,
                         SMEM_SCAN_BYTES);
    rnn_scan10<<<SCAN_CTAS, 256, SMEM_SCAN_BYTES>>>(W_hh, W_out, b_out, y, h);
}

// round 14
// speedup vs baseline: 2.1428x; 2.1428x over previous
#include <cuda_runtime.h>
#include <math.h>
#include <stdint.h>

#define T_STEPS 512
#define BATCH   64
#define IN_DIM  256
#define HID     512
#define OUT_DIM 256
#define BH      (BATCH * HID)        // 32768
#define M_ROWS  (T_STEPS * BATCH)    // 32768

// Scratch (allocation-free rule: __device__ globals)
__device__ float g_xp[(size_t)M_ROWS * HID];   // xp = x@W_ih^T + b_ih + b_hh
__device__ float g_rnn[(size_t)M_ROWS * HID];  // h history (exchange medium)

// ---- barrier state: monotonic flags + persistent epoch ----
#define SCAN_CTAS 128
#define NGROUPS   4     // batch groups
__device__ __align__(128) unsigned g_flags2[NGROUPS][32];  // one 128B line per group
__device__ unsigned g_epoch;

__device__ __forceinline__ unsigned ld_acq(const unsigned* p) {
    unsigned v;
    asm volatile("ld.acquire.gpu.u32 %0, [%1];" : "=r"(v) : "l"(p));
    return v;
}
__device__ __forceinline__ void st_rel(unsigned* p, unsigned v) {
    asm volatile("st.release.gpu.u32 [%0], %1;" :: "l"(p), "r"(v));
}

// fast tanh: rel err ~1e-6, clamped (no NaN)
__device__ __forceinline__ float tanh_fast(float x) {
    float xc = fminf(9.0f, fmaxf(-9.0f, x));
    float e  = exp2f(2.885390081777927f * xc);   // e^(2x)
    return __fdividef(e - 1.0f, e + 1.0f);
}

#define FMA2(acc, a, b) asm("fma.rn.f32x2 %0, %1, %2, %0;" : "+l"(acc) : "l"(a), "l"(b))

// -------------------- SGEMM: C[M,N] = A[M,K] @ Bw[N,K]^T + bias --------------------
template<int BM, int BN, int BK, int TM, int TN, int THREADS>
__global__ __launch_bounds__(THREADS)
void sgemm_bt_bias(const float* __restrict__ A,
                   const float* __restrict__ Bw,
                   const float* __restrict__ bias0,
                   const float* __restrict__ bias1,
                   float* __restrict__ C,
                   int M, int N, int K)
{
    __shared__ float As[BK][BM];
    __shared__ float Bs[BK][BN];

    const int tid = threadIdx.x;
    const int tx  = tid % (BN / TN);
    const int ty  = tid / (BN / TN);
    const int m0  = blockIdx.y * BM;
    const int n0  = blockIdx.x * BN;

    float acc[TM][TN];
    #pragma unroll
    for (int i = 0; i < TM; ++i)
        #pragma unroll
        for (int j = 0; j < TN; ++j) acc[i][j] = 0.f;

    for (int k0 = 0; k0 < K; k0 += BK) {
        #pragma unroll
        for (int i = tid; i < (BM * BK) / 4; i += THREADS) {
            int r  = i / (BK / 4);
            int c4 = i % (BK / 4);
            float4 v = *(const float4*)&A[(size_t)(m0 + r) * K + k0 + c4 * 4];
            As[c4 * 4 + 0][r] = v.x;
            As[c4 * 4 + 1][r] = v.y;
            As[c4 * 4 + 2][r] = v.z;
            As[c4 * 4 + 3][r] = v.w;
        }
        #pragma unroll
        for (int i = tid; i < (BN * BK) / 4; i += THREADS) {
            int r  = i / (BK / 4);
            int c4 = i % (BK / 4);
            float4 v = *(const float4*)&Bw[(size_t)(n0 + r) * K + k0 + c4 * 4];
            Bs[c4 * 4 + 0][r] = v.x;
            Bs[c4 * 4 + 1][r] = v.y;
            Bs[c4 * 4 + 2][r] = v.z;
            Bs[c4 * 4 + 3][r] = v.w;
        }
        __syncthreads();

        #pragma unroll
        for (int kk = 0; kk < BK; ++kk) {
            float aR[TM], bR[TN];
            #pragma unroll
            for (int i = 0; i < TM; ++i) aR[i] = As[kk][ty * TM + i];
            #pragma unroll
            for (int j = 0; j < TN; ++j) bR[j] = Bs[kk][tx * TN + j];
            #pragma unroll
            for (int i = 0; i < TM; ++i)
                #pragma unroll
                for (int j = 0; j < TN; ++j)
                    acc[i][j] += aR[i] * bR[j];
        }
        __syncthreads();
    }

    float bj[TN];
    #pragma unroll
    for (int j = 0; j < TN; ++j) {
        int n = n0 + tx * TN + j;
        bj[j] = bias0[n] + (bias1 ? bias1[n] : 0.f);
    }
    #pragma unroll
    for (int i = 0; i < TM; ++i) {
        int m = m0 + ty * TM + i;
        #pragma unroll
        for (int j = 0; j < TN; ++j) {
            int n = n0 + tx * TN + j;
            C[(size_t)m * N + n] = acc[i][j] + bj[j];
        }
    }
}

// -------------------- fused scan + y GEMM (v11: R12 skeleton, 512 thr k-split) ----
// 128 CTAs = 32 col-groups x 4 batch-groups. CTA: 16 h-cols x 16 batches.
// 512 threads: each h output = 2 threads (half-k), each y output = 4 threads
// (quarter-k, computed inside the barrier window). Partials combined via SMEM
// at the already-existing __syncthreads points.
#define COLS_PER_CTA 16
#define BPC          16
#define OC_CTA       8            // y-cols per col-group (256/32)
#define WS           516
#define HS           520
#define SW_F   (COLS_PER_CTA * WS)   // 8256 floats
#define SWO_F  (OC_CTA * WS)         // 4128
#define SH_F   (BPC * HS)            // 8320
#define SP_F   256                   // h partials (kh=1)
#define SY_F   384                   // y partials (q=1..3)
#define SMEM_SCAN_BYTES ((SW_F + SWO_F + SH_F + SP_F + SY_F) * 4)   // 85376

__global__ __launch_bounds__(512)
void rnn_scan11(const float* __restrict__ Whh,    // [HID, HID]
                const float* __restrict__ Wout,   // [OUT_DIM, HID]
                const float* __restrict__ b_out,  // [OUT_DIM]
                float* __restrict__ y,            // [T, B, O] (d_out)
                float* __restrict__ h_out)        // [B, HID]  (d_out tail)
{
    extern __shared__ float sm[];
    float* sW  = sm;                // [16][WS]
    float* sWo = sW + SW_F;         // [8][WS]
    float* sH  = sWo + SWO_F;       // [16][HS]  h[t-1] staged
    float* sP  = sH + SH_F;         // [256] h partials
    float* sY  = sP + SP_F;         // [384] y partials
    __shared__ unsigned s_base;

    const int tid = threadIdx.x;
    const int bid = blockIdx.x;
    const int bh  = bid & 3;
    const int cg  = bid >> 2;

    // h mapping: inner = tid&255 with R4 warp shape; kh = tid>>8 selects k-half
    const int inner = tid & 255;
    const int kh    = tid >> 8;                   // 0 or 1
    const int w = inner >> 5, l = inner & 31;
    const int c  = ((w & 1) << 3) + (l & 7);      // 0..15
    const int bl = ((w >> 1) << 2) + (l >> 3);    // 0..15
    const int colg = cg * COLS_PER_CTA + c;
    const int b    = bh * BPC + bl;
    const int b0   = bh * BPC;

    // y mapping: o = tid&127 -> (yb, oc); q = tid>>7 selects k-quarter
    const int o   = tid & 127;
    const int q   = tid >> 7;                     // 0..3
    const int yb  = o >> 3;
    const int oc  = o & 7;
    const int ocg = cg * OC_CTA + oc;
    const float bo = b_out[ocg];

    if (tid == 0) s_base = *(volatile unsigned*)&g_epoch;

    // cache W_hh rows [cg*16, +16) and W_out rows [cg*8, +8)
    for (int i = tid; i < COLS_PER_CTA * (HID / 4); i += 512) {
        int r  = i >> 7;
        int k4 = i & 127;
        float4 v = *(const float4*)&Whh[(size_t)(cg * COLS_PER_CTA + r) * HID + k4 * 4];
        *(float4*)&sW[r * WS + k4 * 4] = v;
    }
    for (int i = tid; i < OC_CTA * (HID / 4); i += 512) {
        int r  = i >> 7;
        int k4 = i & 127;
        float4 v = *(const float4*)&Wout[(size_t)(cg * OC_CTA + r) * HID + k4 * 4];
        *(float4*)&sWo[r * WS + k4 * 4] = v;
    }
    __syncthreads();
    const unsigned base = s_base;

    float my_xp = (kh == 0) ? g_xp[(size_t)b * HID + colg] : 0.f;   // t = 0

    const ulonglong2* w2  = (const ulonglong2*)&sW[c * WS] + kh * 64;   // k-half
    const ulonglong2* h2r = (const ulonglong2*)&sH[bl * HS] + kh * 64;
    const ulonglong2* wo2 = (const ulonglong2*)&sWo[oc * WS] + q * 32;  // k-quarter
    const ulonglong2* hy2 = (const ulonglong2*)&sH[yb * HS] + q * 32;

    for (int t = 0; t < T_STEPS; ++t) {
        // ---- h[t] partial over this thread's k-half ----
        float part = 0.f;
        if (t > 0) {
            unsigned long long a01 = 0ull, a23 = 0ull;
            #pragma unroll 8
            for (int k4 = 0; k4 < 64; ++k4) {
                ulonglong2 hv = h2r[k4];
                ulonglong2 wv = w2[k4];
                FMA2(a01, hv.x, wv.x);
                FMA2(a23, hv.y, wv.y);
            }
            float s0, s1, s2, s3;
            asm("mov.b64 {%0, %1}, %2;" : "=f"(s0), "=f"(s1) : "l"(a01));
            asm("mov.b64 {%0, %1}, %2;" : "=f"(s2), "=f"(s3) : "l"(a23));
            part = (s0 + s1) + (s2 + s3);
        }
        if (kh) sP[inner] = part;
        __syncthreads();                      // sP visible

        if (!kh) {
            float hn = tanh_fast(my_xp + part + sP[inner]);
            g_rnn[(size_t)t * BH + (size_t)b * HID + colg] = hn;
            if (t == T_STEPS - 1)
                h_out[(size_t)b * HID + colg] = hn;
        }
        __syncthreads();                      // all h[t] stores issued
        if (tid == 0)
            st_rel(&g_flags2[bh][cg], base + (unsigned)t + 1u);  // publish

        // ---- gap work: y[t-1] quarter-partial from STABLE sH (= h[t-1]) ----
        float ypart = 0.f;
        if (t > 0) {
            unsigned long long a01 = 0ull, a23 = 0ull;
            #pragma unroll 8
            for (int k4 = 0; k4 < 32; ++k4) {
                ulonglong2 hv = hy2[k4];
                ulonglong2 wv = wo2[k4];
                FMA2(a01, hv.x, wv.x);
                FMA2(a23, hv.y, wv.y);
            }
            float s0, s1, s2, s3;
            asm("mov.b64 {%0, %1}, %2;" : "=f"(s0), "=f"(s1) : "l"(a01));
            asm("mov.b64 {%0, %1}, %2;" : "=f"(s2), "=f"(s3) : "l"(a23));
            ypart = (s0 + s1) + (s2 + s3);
            if (q) sY[(q - 1) * 128 + o] = ypart;
        }

        // ---- barrier: wait for whole bh group to publish h[t] ----
        const unsigned target = base + (unsigned)t + 1u;
        if (tid < 32) {
            bool ok;
            do {
                unsigned v = ld_acq(&g_flags2[bh][tid]);
                ok = __all_sync(0xffffffffu, (int)(v - target) >= 0);
            } while (!ok);
        }
        __syncthreads();                      // flags seen; sY visible

        if (t > 0 && q == 0)
            y[(size_t)(t - 1) * (BATCH * OUT_DIM) + (size_t)(b0 + yb) * OUT_DIM + ocg]
                = bo + ypart + sY[o] + sY[128 + o] + sY[256 + o];

        // ---- stage h[t] rows b0..b0+15 into sH; prefetch next xp ----
        const float* src = &g_rnn[(size_t)t * BH + (size_t)b0 * HID];
        #pragma unroll
        for (int i = tid; i < BPC * (HID / 4); i += 512) {
            int r  = i >> 7;
            int k4 = i & 127;
            float4 v = *(const float4*)&src[(size_t)r * HID + k4 * 4];
            *(float4*)&sH[r * HS + k4 * 4] = v;
        }
        if (!kh && t + 1 < T_STEPS)
            my_xp = g_xp[(size_t)(t + 1) * BH + (size_t)b * HID + colg];
        __syncthreads();                      // sH = h[t] complete
    }

    // ---- epilogue: y[511] from sH = h[511] ----
    {
        unsigned long long a01 = 0ull, a23 = 0ull;
        #pragma unroll 8
        for (int k4 = 0; k4 < 32; ++k4) {
            ulonglong2 hv = hy2[k4];
            ulonglong2 wv = wo2[k4];
            FMA2(a01, hv.x, wv.x);
            FMA2(a23, hv.y, wv.y);
        }
        float s0, s1, s2, s3;
        asm("mov.b64 {%0, %1}, %2;" : "=f"(s0), "=f"(s1) : "l"(a01));
        asm("mov.b64 {%0, %1}, %2;" : "=f"(s2), "=f"(s3) : "l"(a23));
        float ypart = (s0 + s1) + (s2 + s3);
        if (q) sY[(q - 1) * 128 + o] = ypart;
        __syncthreads();
        if (q == 0)
            y[(size_t)(T_STEPS - 1) * (BATCH * OUT_DIM) + (size_t)(b0 + yb) * OUT_DIM + ocg]
                = bo + ypart + sY[o] + sY[128 + o] + sY[256 + o];
    }

    // advance epoch for the next launch (monotonic flags)
    if (bid == 0 && tid == 0)
        *(volatile unsigned*)&g_epoch = base + (unsigned)T_STEPS;
}

__global__ void dummy_k() {}

// -------------------- launch --------------------
extern "C" void kernel_launch(void* const* d_in, const int* in_sizes, int n_in,
                              void* d_out, int out_size)
{
    const float* x     = (const float*)d_in[0];
    const float* W_ih  = (const float*)d_in[1];
    const float* W_hh  = (const float*)d_in[2];
    const float* b_ih  = (const float*)d_in[3];
    const float* b_hh  = (const float*)d_in[4];
    const float* W_out = (const float*)d_in[5];
    const float* b_out = (const float*)d_in[6];

    float* y = (float*)d_out;                             // [T,B,O]
    float* h = y + (size_t)T_STEPS * BATCH * OUT_DIM;     // [1,B,H]

    float* xp = nullptr;
    cudaGetSymbolAddress((void**)&xp, g_xp);

    // K1: xp = x @ W_ih^T + b_ih + b_hh    (M=32768, N=512, K=256)
    {
        dim3 grid(HID / 64, M_ROWS / 128);
        sgemm_bt_bias<128, 64, 16, 8, 4, 256><<<grid, 256>>>(
            x, W_ih, b_ih, b_hh, xp, M_ROWS, HID, IN_DIM);
    }

    // two dummies so the fused scan sits at global launch #6 for ncu (-s 5 -c 1)
    dummy_k<<<1, 32>>>();
    dummy_k<<<1, 32>>>();

    // K2: fused recurrence + output GEMM; writes y + h_last
    cudaFuncSetAttribute(rnn_scan11, cudaFuncAttributeMaxDynamicSharedMemorySize,
                         SMEM_SCAN_BYTES);
    rnn_scan11<<<SCAN_CTAS, 512, SMEM_SCAN_BYTES>>>(W_hh, W_out, b_out, y, h);
}